// round 16
// baseline (speedup 1.0000x reference)
#include <cuda_runtime.h>
#include <cuda_fp16.h>
#include <cstdint>
#include <math.h>

// ===================== constants =====================
#define BMAX   4096
#define DMAX   2048
#define BM 128
#define BN 128
#define TBK 64                      // fp16 K per chunk = 128 bytes/row
#define STAGES 3
#define A_BYTES (BM*TBK*2)          // 16384
#define B_BYTES (BN*TBK*2)          // 16384
#define STAGE_BYTES (A_BYTES+B_BYTES)   // 32768
#define META_OFF (STAGES*STAGE_BYTES)   // 98304 (labels/sq, 2 KB)
#define SMEM_TOTAL (META_OFF + 2048)    // 100352 -> 2 CTAs/SM
#define NCHUNK (BMAX/BN)            // 32

#define POS_EMPTY 0ull
#define NEG_EMPTY 0xFFFFFFFFFFFFFFFFull

// ===================== device scratch =====================
__device__ __half g_ebf[(size_t)BMAX * DMAX];
__device__ float g_sq[BMAX];
__device__ unsigned long long g_pos[NCHUNK][BMAX];
__device__ unsigned long long g_neg[NCHUNK][BMAX];
__device__ int   g_valid[BMAX];
__device__ float g_loss[BMAX];

// ===================== helpers =====================
__device__ __forceinline__ uint32_t smem_u32(const void* p) {
    uint32_t a;
    asm("{ .reg .u64 t; cvta.to.shared.u64 t, %1; cvt.u32.u64 %0, t; }" : "=r"(a) : "l"(p));
    return a;
}
__device__ __forceinline__ void cpa16(uint32_t s, const void* g) {
    asm volatile("cp.async.cg.shared.global [%0], [%1], 16;" :: "r"(s), "l"(g));
}
#define CPA_COMMIT() asm volatile("cp.async.commit_group;" ::: "memory")
#define CPA_WAIT(N)  asm volatile("cp.async.wait_group %0;" :: "n"(N) : "memory")

__device__ __forceinline__ void ldsm4(uint32_t* r, uint32_t addr) {
    asm volatile("ldmatrix.sync.aligned.m8n8.x4.shared.b16 {%0,%1,%2,%3}, [%4];"
                 : "=r"(r[0]), "=r"(r[1]), "=r"(r[2]), "=r"(r[3]) : "r"(addr));
}
// f16-accumulate HMMA: D/C are 2 regs of packed half2 {d0,d1},{d2,d3}
__device__ __forceinline__ void mma16816h(uint32_t* c, const uint32_t* a, const uint32_t* b) {
    asm volatile(
        "mma.sync.aligned.m16n8k16.row.col.f16.f16.f16.f16 "
        "{%0,%1}, {%2,%3,%4,%5}, {%6,%7}, {%0,%1};"
        : "+r"(c[0]), "+r"(c[1])
        : "r"(a[0]), "r"(a[1]), "r"(a[2]), "r"(a[3]), "r"(b[0]), "r"(b[1]));
}

// packed selection keys: d2 >= 0 so float bits are order-preserving.
__device__ __forceinline__ unsigned long long packPos(float d2, int j) {
    return ((unsigned long long)__float_as_uint(d2) << 32) |
           (unsigned long long)(0xFFFFFFFFu - (uint32_t)j);
}
__device__ __forceinline__ unsigned long long packNeg(float d2, int j) {
    return ((unsigned long long)__float_as_uint(d2) << 32) | (unsigned long long)(uint32_t)j;
}
__device__ __forceinline__ unsigned long long u64max(unsigned long long a, unsigned long long b) {
    return a > b ? a : b;
}
__device__ __forceinline__ unsigned long long u64min(unsigned long long a, unsigned long long b) {
    return a < b ? a : b;
}

// ===================== kernel 1: fp32 -> fp16 + row sumsq (warp-per-row) ==========
__global__ __launch_bounds__(256) void convKernel(const float* __restrict__ emb, int D) {
    const int warp = threadIdx.x >> 5;
    const int lane = threadIdx.x & 31;
    const int i = blockIdx.x * 8 + warp;
    const float4* row = reinterpret_cast<const float4*>(emb + (size_t)i * D);
    __half2* orow = reinterpret_cast<__half2*>(g_ebf + (size_t)i * D);

    float s = 0.f;
#pragma unroll
    for (int t = 0; t < 16; t++) {
        int k = lane + 32 * t;
        float4 v = row[k];
        s += v.x * v.x + v.y * v.y + v.z * v.z + v.w * v.w;
        orow[2 * k]     = __floats2half2_rn(v.x, v.y);
        orow[2 * k + 1] = __floats2half2_rn(v.z, v.w);
    }
#pragma unroll
    for (int off = 16; off > 0; off >>= 1)
        s += __shfl_down_sync(0xFFFFFFFFu, s, off);
    if (lane == 0) g_sq[i] = s;
}

// ===================== kernel 2: fp16 HMMA GEMM (upper triangle), 64x64 warp tiles ==========
__device__ __forceinline__ void load_chunk(int tid, uint32_t sbase, int s,
                                           int iBase, int jBase, int c, int D) {
    uint32_t sA = sbase + s * STAGE_BYTES;
    uint32_t sB = sA + A_BYTES;
    int k0 = c * TBK;
    const char* gA = (const char*)(g_ebf + (size_t)iBase * D + k0);
    const char* gB = (const char*)(g_ebf + (size_t)jBase * D + k0);
#pragma unroll
    for (int t = 0; t < 8; t++) {
        int f = tid + t * 128;
        int row = f >> 3, c16 = f & 7;
        int colb = c16 * 16;
        uint32_t off = (uint32_t)(row * 128 + (colb ^ ((row & 7) << 4)));
        cpa16(sA + off, gA + (size_t)row * (size_t)(D * 2) + colb);
    }
#pragma unroll
    for (int t = 0; t < 8; t++) {
        int f = tid + t * 128;
        int row = f >> 3, c16 = f & 7;
        int colb = c16 * 16;
        uint32_t off = (uint32_t)(row * 128 + (colb ^ ((row & 7) << 4)));
        cpa16(sB + off, gB + (size_t)row * (size_t)(D * 2) + colb);
    }
    CPA_COMMIT();
}

__global__ __launch_bounds__(128, 2) void distKernel(const int* __restrict__ labels,
                                                     int B, int D) {
    extern __shared__ char sm[];
    uint32_t sbase = smem_u32(sm);

    const int tid  = threadIdx.x;
    const int wid  = tid >> 5;
    const int lane = tid & 31;
    const int warpM = wid & 1;       // 0..1 (64 rows each)
    const int warpN = wid >> 1;      // 0..1 (64 cols each)

    // decode upper-triangular tile (bi <= bj)
    const int nb = B / BM;           // 32
    int bi = 0, rem = blockIdx.x;
    while (rem >= nb - bi) { rem -= nb - bi; bi++; }
    const int bj = bi + rem;
    const int iBase = bi * BM;
    const int jBase = bj * BN;
    const bool diag = (bi == bj);

    int*   sLabJ = (int*)  (sm + META_OFF);
    float* sSqJ  = (float*)(sm + META_OFF + 512);
    int*   sLabI = (int*)  (sm + META_OFF + 1024);
    float* sSqI  = (float*)(sm + META_OFF + 1536);
    unsigned long long* sRowP = (unsigned long long*)(sm);
    unsigned long long* sRowN = (unsigned long long*)(sm + 2048);
    unsigned long long* sColP = (unsigned long long*)(sm + 4096);
    unsigned long long* sColN = (unsigned long long*)(sm + 6144);

    if (tid < 128) {
        sLabJ[tid] = labels[jBase + tid];
        sSqJ[tid]  = g_sq[jBase + tid];
        sLabI[tid] = labels[iBase + tid];
        sSqI[tid]  = g_sq[iBase + tid];
    }

    const int rowA_l = (lane & 7) + ((lane >> 3) & 1) * 8;
    const int colA_b = (lane >> 4) * 16;
    const int rowB_l = (lane & 7) + (lane >> 4) * 8;
    const int colB_b = ((lane >> 3) & 1) * 16;

    int aRow[4], bRow[4];
#pragma unroll
    for (int mf = 0; mf < 4; mf++) aRow[mf] = warpM * 64 + mf * 16 + rowA_l;
#pragma unroll
    for (int nf = 0; nf < 4; nf++) bRow[nf] = warpN * 64 + nf * 16 + rowB_l;

    // fp32 master accumulators
    float acc[4][8][4];
#pragma unroll
    for (int a = 0; a < 4; a++)
#pragma unroll
        for (int b = 0; b < 8; b++)
#pragma unroll
            for (int c = 0; c < 4; c++) acc[a][b][c] = 0.f;

    const int nch = D / TBK;     // 32

    load_chunk(tid, sbase, 0, iBase, jBase, 0, D);
    load_chunk(tid, sbase, 1, iBase, jBase, 1, D);

    for (int c = 0; c < nch; c++) {
        if (c == nch - 1) { CPA_WAIT(0); } else { CPA_WAIT(1); }
        __syncthreads();
        if (c + 2 < nch)
            load_chunk(tid, sbase, (c + 2) % STAGES, iBase, jBase, c + 2, D);

        uint32_t sA = sbase + (c % STAGES) * STAGE_BYTES;
        uint32_t sB = sA + A_BYTES;

        // f16 chunk accumulators (zeroed per chunk; K=64 partial sums stay tiny)
        uint32_t accH[4][8][2];
#pragma unroll
        for (int a = 0; a < 4; a++)
#pragma unroll
            for (int b = 0; b < 8; b++) { accH[a][b][0] = 0u; accH[a][b][1] = 0u; }

#pragma unroll
        for (int ks = 0; ks < TBK / 16; ks++) {
            uint32_t aF[16], bF[16];
#pragma unroll
            for (int mf = 0; mf < 4; mf++) {
                int r = aRow[mf];
                ldsm4(aF + mf * 4, sA + r * 128 + ((ks * 32 + colA_b) ^ ((r & 7) << 4)));
            }
#pragma unroll
            for (int nf = 0; nf < 4; nf++) {
                int r = bRow[nf];
                ldsm4(bF + nf * 4, sB + r * 128 + ((ks * 32 + colB_b) ^ ((r & 7) << 4)));
            }
#pragma unroll
            for (int mf = 0; mf < 4; mf++)
#pragma unroll
                for (int n8 = 0; n8 < 8; n8++)
                    mma16816h(accH[mf][n8], aF + mf * 4, bF + n8 * 2);
        }

        // promote chunk result to fp32 master
#pragma unroll
        for (int mf = 0; mf < 4; mf++)
#pragma unroll
            for (int n8 = 0; n8 < 8; n8++) {
                float2 lo = __half22float2(*reinterpret_cast<__half2*>(&accH[mf][n8][0]));
                float2 hi = __half22float2(*reinterpret_cast<__half2*>(&accH[mf][n8][1]));
                acc[mf][n8][0] += lo.x;
                acc[mf][n8][1] += lo.y;
                acc[mf][n8][2] += hi.x;
                acc[mf][n8][3] += hi.y;
            }
    }
    __syncthreads();   // stage smem now reusable

    // ---- epilogue: d^2 + dual hard pos/neg selection (packed u64 keys) ----
    const int g = lane >> 2;
    const int q = lane & 3;

    unsigned long long ckP[16], ckN[16];
#pragma unroll
    for (int t = 0; t < 16; t++) { ckP[t] = POS_EMPTY; ckN[t] = NEG_EMPTY; }

#pragma unroll
    for (int mf = 0; mf < 4; mf++) {
#pragma unroll
        for (int h = 0; h < 2; h++) {
            int rl   = warpM * 64 + mf * 16 + h * 8 + g;
            int iRow = iBase + rl;
            float sqi = sSqI[rl];
            int   lab = sLabI[rl];
            unsigned long long pKey = POS_EMPTY, nKey = NEG_EMPTY;
#pragma unroll
            for (int t = 0; t < 16; t++) {
                int n8 = t >> 1, cc = t & 1;
                int jj = warpN * 64 + n8 * 8 + q * 2 + cc;
                int j  = jBase + jj;
                float d2 = fmaxf(sqi + sSqJ[jj] - 2.f * acc[mf][n8][h * 2 + cc], 0.f);
                if (sLabJ[jj] == lab) {
                    if (j != iRow) {
                        pKey  = u64max(pKey, packPos(d2, j));
                        ckP[t] = u64max(ckP[t], packPos(d2, iRow));
                    }
                } else {
                    nKey  = u64min(nKey, packNeg(d2, j));
                    ckN[t] = u64min(ckN[t], packNeg(d2, iRow));
                }
            }
#pragma unroll
            for (int off = 1; off <= 2; off <<= 1) {
                pKey = u64max(pKey, __shfl_xor_sync(0xFFFFFFFFu, pKey, off));
                nKey = u64min(nKey, __shfl_xor_sync(0xFFFFFFFFu, nKey, off));
            }
            if (q == 0) {
                sRowP[rl * 2 + warpN] = pKey;
                sRowN[rl * 2 + warpN] = nKey;
            }
        }
    }

    if (!diag) {
#pragma unroll
        for (int t = 0; t < 16; t++) {
#pragma unroll
            for (int off = 4; off <= 16; off <<= 1) {
                ckP[t] = u64max(ckP[t], __shfl_xor_sync(0xFFFFFFFFu, ckP[t], off));
                ckN[t] = u64min(ckN[t], __shfl_xor_sync(0xFFFFFFFFu, ckN[t], off));
            }
        }
        if (g == 0) {
#pragma unroll
            for (int t = 0; t < 16; t++) {
                int n8 = t >> 1, cc = t & 1;
                int jj = warpN * 64 + n8 * 8 + q * 2 + cc;
                sColP[jj * 2 + warpM] = ckP[t];
                sColN[jj * 2 + warpM] = ckN[t];
            }
        }
    }
    __syncthreads();

    if (tid < 128) {
        unsigned long long pKey = u64max(sRowP[tid * 2], sRowP[tid * 2 + 1]);
        unsigned long long nKey = u64min(sRowN[tid * 2], sRowN[tid * 2 + 1]);
        int iRow = iBase + tid;
        g_pos[bj][iRow] = pKey;
        g_neg[bj][iRow] = nKey;

        if (!diag) {
            unsigned long long cp = u64max(sColP[tid * 2], sColP[tid * 2 + 1]);
            unsigned long long cn = u64min(sColN[tid * 2], sColN[tid * 2 + 1]);
            int jRow = jBase + tid;
            g_pos[bi][jRow] = cp;
            g_neg[bi][jRow] = cn;
        }
    }
}

// ===================== kernel 3: fused merge + exact dp/dn loss =====================
__global__ __launch_bounds__(256) void lossKernel(const float* __restrict__ emb,
                                                  int D, int B) {
    int i = blockIdx.x;
    __shared__ int s_hp, s_hn, s_val;

    if (threadIdx.x < 32) {
        int c = threadIdx.x;    // NCHUNK == 32
        unsigned long long pKey = g_pos[c][i];
        unsigned long long nKey = g_neg[c][i];
#pragma unroll
        for (int off = 16; off > 0; off >>= 1) {
            pKey = u64max(pKey, __shfl_xor_sync(0xFFFFFFFFu, pKey, off));
            nKey = u64min(nKey, __shfl_xor_sync(0xFFFFFFFFu, nKey, off));
        }
        if (threadIdx.x == 0) {
            int hp = (int)(0xFFFFFFFFu - (uint32_t)pKey);
            int hn = (int)(uint32_t)nKey;
            int vp = (pKey != POS_EMPTY);
            int vn = (nKey != NEG_EMPTY);
            s_hp  = (vp && hp >= 0 && hp < B) ? hp : 0;
            s_hn  = (vn && hn >= 0 && hn < B) ? hn : 0;
            s_val = vp && vn;
        }
    }
    __syncthreads();

    int hp = s_hp, hn = s_hn;
    const float* a = emb + (size_t)i  * D;
    const float* p = emb + (size_t)hp * D;
    const float* n = emb + (size_t)hn * D;
    float sp = 0.f, sn = 0.f;
    for (int k = threadIdx.x * 4; k < D; k += blockDim.x * 4) {
        float4 va = *reinterpret_cast<const float4*>(a + k);
        float4 vp = *reinterpret_cast<const float4*>(p + k);
        float4 vn = *reinterpret_cast<const float4*>(n + k);
        float d;
        d = va.x - vp.x + 1e-6f; sp += d * d;
        d = va.y - vp.y + 1e-6f; sp += d * d;
        d = va.z - vp.z + 1e-6f; sp += d * d;
        d = va.w - vp.w + 1e-6f; sp += d * d;
        d = va.x - vn.x + 1e-6f; sn += d * d;
        d = va.y - vn.y + 1e-6f; sn += d * d;
        d = va.z - vn.z + 1e-6f; sn += d * d;
        d = va.w - vn.w + 1e-6f; sn += d * d;
    }
    for (int off = 16; off > 0; off >>= 1) {
        sp += __shfl_down_sync(0xFFFFFFFFu, sp, off);
        sn += __shfl_down_sync(0xFFFFFFFFu, sn, off);
    }
    __shared__ float wsp[8], wsn[8];
    int w = threadIdx.x >> 5;
    if ((threadIdx.x & 31) == 0) { wsp[w] = sp; wsn[w] = sn; }
    __syncthreads();
    if (threadIdx.x == 0) {
        float tp = 0.f, tn = 0.f;
#pragma unroll
        for (int ww = 0; ww < 8; ww++) { tp += wsp[ww]; tn += wsn[ww]; }
        float per = fmaxf(sqrtf(tp) - sqrtf(tn) + 0.3f, 0.f);
        g_loss[i]  = s_val ? per : 0.f;
        g_valid[i] = s_val;
    }
}

// ===================== kernel 4: final reduction =====================
__global__ void finalKernel(float* __restrict__ out, int B) {
    __shared__ float ssum[1024];
    __shared__ int   scnt[1024];
    float s = 0.f; int c = 0;
    for (int i = threadIdx.x; i < B; i += 1024) {
        s += g_loss[i];
        c += g_valid[i];
    }
    ssum[threadIdx.x] = s;
    scnt[threadIdx.x] = c;
    __syncthreads();
    for (int off = 512; off > 0; off >>= 1) {
        if (threadIdx.x < off) {
            ssum[threadIdx.x] += ssum[threadIdx.x + off];
            scnt[threadIdx.x] += scnt[threadIdx.x + off];
        }
        __syncthreads();
    }
    if (threadIdx.x == 0)
        out[0] = (scnt[0] > 0) ? ssum[0] / (float)scnt[0] : 0.f;
}

// ===================== launch =====================
extern "C" void kernel_launch(void* const* d_in, const int* in_sizes, int n_in,
                              void* d_out, int out_size) {
    const float* emb    = (const float*)d_in[0];
    const int*   labels = (const int*)d_in[1];
    float*       out    = (float*)d_out;
    int B = in_sizes[1];
    int D = in_sizes[0] / B;

    cudaFuncSetAttribute(distKernel, cudaFuncAttributeMaxDynamicSharedMemorySize, SMEM_TOTAL);

    convKernel<<<B / 8, 256>>>(emb, D);
    int nb = B / BM;
    int ntiles = nb * (nb + 1) / 2;
    distKernel<<<ntiles, 128, SMEM_TOTAL>>>(labels, B, D);
    lossKernel<<<B, 256>>>(emb, D, B);
    finalKernel<<<1, 1024>>>(out, B);
}

// round 17
// speedup vs baseline: 1.2143x; 1.2143x over previous
#include <cuda_runtime.h>
#include <cuda_bf16.h>
#include <cstdint>
#include <math.h>

// ===================== constants =====================
#define BMAX   4096
#define DMAX   2048
#define BM 128
#define BN 128
#define TBK 64                      // bf16 K per chunk = 128 bytes/row
#define STAGES 3
#define A_BYTES (BM*TBK*2)          // 16384
#define B_BYTES (BN*TBK*2)          // 16384
#define STAGE_BYTES (A_BYTES+B_BYTES)   // 32768
#define META_OFF (STAGES*STAGE_BYTES)   // 98304 (labels/sq, 2 KB)
#define SMEM_TOTAL (META_OFF + 2048)    // 100352 -> 2 CTAs/SM
#define NCHUNK (BMAX/BN)            // 32

#define POS_EMPTY 0ull
#define NEG_EMPTY 0xFFFFFFFFFFFFFFFFull

// ===================== device scratch =====================
__device__ __nv_bfloat16 g_ebf[(size_t)BMAX * DMAX];
__device__ float g_sq[BMAX];
__device__ unsigned long long g_pos[NCHUNK][BMAX];
__device__ unsigned long long g_neg[NCHUNK][BMAX];
__device__ int   g_valid[BMAX];
__device__ float g_loss[BMAX];

// ===================== helpers =====================
__device__ __forceinline__ uint32_t smem_u32(const void* p) {
    uint32_t a;
    asm("{ .reg .u64 t; cvta.to.shared.u64 t, %1; cvt.u32.u64 %0, t; }" : "=r"(a) : "l"(p));
    return a;
}
__device__ __forceinline__ void cpa16(uint32_t s, const void* g) {
    asm volatile("cp.async.cg.shared.global [%0], [%1], 16;" :: "r"(s), "l"(g));
}
#define CPA_COMMIT() asm volatile("cp.async.commit_group;" ::: "memory")
#define CPA_WAIT(N)  asm volatile("cp.async.wait_group %0;" :: "n"(N) : "memory")

__device__ __forceinline__ void ldsm4(uint32_t* r, uint32_t addr) {
    asm volatile("ldmatrix.sync.aligned.m8n8.x4.shared.b16 {%0,%1,%2,%3}, [%4];"
                 : "=r"(r[0]), "=r"(r[1]), "=r"(r[2]), "=r"(r[3]) : "r"(addr));
}
__device__ __forceinline__ void mma16816(float* c, const uint32_t* a, const uint32_t* b) {
    asm volatile(
        "mma.sync.aligned.m16n8k16.row.col.f32.bf16.bf16.f32 "
        "{%0,%1,%2,%3}, {%4,%5,%6,%7}, {%8,%9}, {%0,%1,%2,%3};"
        : "+f"(c[0]), "+f"(c[1]), "+f"(c[2]), "+f"(c[3])
        : "r"(a[0]), "r"(a[1]), "r"(a[2]), "r"(a[3]), "r"(b[0]), "r"(b[1]));
}

// packed selection keys: d2 >= 0 so float bits are order-preserving.
// pos (argmax, lowest index wins ties): key = (bits(d2)<<32) | (0xFFFFFFFF - j), take max
// neg (argmin, lowest index wins ties): key = (bits(d2)<<32) | j,                take min
__device__ __forceinline__ unsigned long long packPos(float d2, int j) {
    return ((unsigned long long)__float_as_uint(d2) << 32) |
           (unsigned long long)(0xFFFFFFFFu - (uint32_t)j);
}
__device__ __forceinline__ unsigned long long packNeg(float d2, int j) {
    return ((unsigned long long)__float_as_uint(d2) << 32) | (unsigned long long)(uint32_t)j;
}
__device__ __forceinline__ unsigned long long u64max(unsigned long long a, unsigned long long b) {
    return a > b ? a : b;
}
__device__ __forceinline__ unsigned long long u64min(unsigned long long a, unsigned long long b) {
    return a < b ? a : b;
}

// ===================== kernel 1: fp32 -> bf16 + row sumsq (warp-per-row) ==========
__global__ __launch_bounds__(256) void convKernel(const float* __restrict__ emb, int D) {
    const int warp = threadIdx.x >> 5;
    const int lane = threadIdx.x & 31;
    const int i = blockIdx.x * 8 + warp;
    const float4* row = reinterpret_cast<const float4*>(emb + (size_t)i * D);
    __nv_bfloat162* orow = reinterpret_cast<__nv_bfloat162*>(g_ebf + (size_t)i * D);

    float s = 0.f;
#pragma unroll
    for (int t = 0; t < 16; t++) {
        int k = lane + 32 * t;
        float4 v = row[k];
        s += v.x * v.x + v.y * v.y + v.z * v.z + v.w * v.w;
        __nv_bfloat162 h0, h1;
        h0.x = __float2bfloat16(v.x); h0.y = __float2bfloat16(v.y);
        h1.x = __float2bfloat16(v.z); h1.y = __float2bfloat16(v.w);
        orow[2 * k] = h0; orow[2 * k + 1] = h1;
    }
#pragma unroll
    for (int off = 16; off > 0; off >>= 1)
        s += __shfl_down_sync(0xFFFFFFFFu, s, off);
    if (lane == 0) g_sq[i] = s;
}

// ===================== kernel 2: bf16 HMMA GEMM (upper triangle), 64x64 warp tiles ==========
__device__ __forceinline__ void load_chunk(int tid, uint32_t sbase, int s,
                                           int iBase, int jBase, int c, int D) {
    uint32_t sA = sbase + s * STAGE_BYTES;
    uint32_t sB = sA + A_BYTES;
    int k0 = c * TBK;
    const char* gA = (const char*)(g_ebf + (size_t)iBase * D + k0);
    const char* gB = (const char*)(g_ebf + (size_t)jBase * D + k0);
#pragma unroll
    for (int t = 0; t < 8; t++) {
        int f = tid + t * 128;
        int row = f >> 3, c16 = f & 7;
        int colb = c16 * 16;
        uint32_t off = (uint32_t)(row * 128 + (colb ^ ((row & 7) << 4)));
        cpa16(sA + off, gA + (size_t)row * (size_t)(D * 2) + colb);
    }
#pragma unroll
    for (int t = 0; t < 8; t++) {
        int f = tid + t * 128;
        int row = f >> 3, c16 = f & 7;
        int colb = c16 * 16;
        uint32_t off = (uint32_t)(row * 128 + (colb ^ ((row & 7) << 4)));
        cpa16(sB + off, gB + (size_t)row * (size_t)(D * 2) + colb);
    }
    CPA_COMMIT();
}

__global__ __launch_bounds__(128, 2) void distKernel(const int* __restrict__ labels,
                                                     int B, int D) {
    extern __shared__ char sm[];
    uint32_t sbase = smem_u32(sm);

    const int tid  = threadIdx.x;
    const int wid  = tid >> 5;
    const int lane = tid & 31;
    const int warpM = wid & 1;       // 0..1 (64 rows each)
    const int warpN = wid >> 1;      // 0..1 (64 cols each)

    // decode upper-triangular tile (bi <= bj)
    const int nb = B / BM;           // 32
    int bi = 0, rem = blockIdx.x;
    while (rem >= nb - bi) { rem -= nb - bi; bi++; }
    const int bj = bi + rem;
    const int iBase = bi * BM;
    const int jBase = bj * BN;
    const bool diag = (bi == bj);

    int*   sLabJ = (int*)  (sm + META_OFF);
    float* sSqJ  = (float*)(sm + META_OFF + 512);
    int*   sLabI = (int*)  (sm + META_OFF + 1024);
    float* sSqI  = (float*)(sm + META_OFF + 1536);
    // selection-exchange buffers reuse stage-0 smem (epilogue only)
    unsigned long long* sRowP = (unsigned long long*)(sm);          // 128*2 u64 = 2KB
    unsigned long long* sRowN = (unsigned long long*)(sm + 2048);
    unsigned long long* sColP = (unsigned long long*)(sm + 4096);
    unsigned long long* sColN = (unsigned long long*)(sm + 6144);

    if (tid < 128) {
        sLabJ[tid] = labels[jBase + tid];
        sSqJ[tid]  = g_sq[jBase + tid];
        sLabI[tid] = labels[iBase + tid];
        sSqI[tid]  = g_sq[iBase + tid];
    }

    const int rowA_l = (lane & 7) + ((lane >> 3) & 1) * 8;
    const int colA_b = (lane >> 4) * 16;
    const int rowB_l = (lane & 7) + (lane >> 4) * 8;
    const int colB_b = ((lane >> 3) & 1) * 16;

    int aRow[4], bRow[4];
#pragma unroll
    for (int mf = 0; mf < 4; mf++) aRow[mf] = warpM * 64 + mf * 16 + rowA_l;
#pragma unroll
    for (int nf = 0; nf < 4; nf++) bRow[nf] = warpN * 64 + nf * 16 + rowB_l;

    float acc[4][8][4];
#pragma unroll
    for (int a = 0; a < 4; a++)
#pragma unroll
        for (int b = 0; b < 8; b++)
#pragma unroll
            for (int c = 0; c < 4; c++) acc[a][b][c] = 0.f;

    const int nch = D / TBK;     // 32

    load_chunk(tid, sbase, 0, iBase, jBase, 0, D);
    load_chunk(tid, sbase, 1, iBase, jBase, 1, D);

    for (int c = 0; c < nch; c++) {
        if (c == nch - 1) { CPA_WAIT(0); } else { CPA_WAIT(1); }
        __syncthreads();
        if (c + 2 < nch)
            load_chunk(tid, sbase, (c + 2) % STAGES, iBase, jBase, c + 2, D);

        uint32_t sA = sbase + (c % STAGES) * STAGE_BYTES;
        uint32_t sB = sA + A_BYTES;
#pragma unroll
        for (int ks = 0; ks < TBK / 16; ks++) {
            uint32_t aF[16], bF[16];
#pragma unroll
            for (int mf = 0; mf < 4; mf++) {
                int r = aRow[mf];
                ldsm4(aF + mf * 4, sA + r * 128 + ((ks * 32 + colA_b) ^ ((r & 7) << 4)));
            }
#pragma unroll
            for (int nf = 0; nf < 4; nf++) {
                int r = bRow[nf];
                ldsm4(bF + nf * 4, sB + r * 128 + ((ks * 32 + colB_b) ^ ((r & 7) << 4)));
            }
#pragma unroll
            for (int mf = 0; mf < 4; mf++)
#pragma unroll
                for (int n8 = 0; n8 < 8; n8++)
                    mma16816(acc[mf][n8], aF + mf * 4, bF + n8 * 2);
        }
    }
    __syncthreads();   // stage smem now reusable

    // ---- epilogue: d^2 + dual hard pos/neg selection (packed u64 keys) ----
    const int g = lane >> 2;
    const int q = lane & 3;

    unsigned long long ckP[16], ckN[16];
#pragma unroll
    for (int t = 0; t < 16; t++) { ckP[t] = POS_EMPTY; ckN[t] = NEG_EMPTY; }

#pragma unroll
    for (int mf = 0; mf < 4; mf++) {
#pragma unroll
        for (int h = 0; h < 2; h++) {
            int rl   = warpM * 64 + mf * 16 + h * 8 + g;
            int iRow = iBase + rl;
            float sqi = sSqI[rl];
            int   lab = sLabI[rl];
            unsigned long long pKey = POS_EMPTY, nKey = NEG_EMPTY;
#pragma unroll
            for (int t = 0; t < 16; t++) {
                int n8 = t >> 1, cc = t & 1;
                int jj = warpN * 64 + n8 * 8 + q * 2 + cc;
                int j  = jBase + jj;
                float d2 = fmaxf(sqi + sSqJ[jj] - 2.f * acc[mf][n8][h * 2 + cc], 0.f);
                if (sLabJ[jj] == lab) {
                    if (j != iRow) {
                        pKey  = u64max(pKey, packPos(d2, j));
                        ckP[t] = u64max(ckP[t], packPos(d2, iRow));
                    }
                } else {
                    nKey  = u64min(nKey, packNeg(d2, j));
                    ckN[t] = u64min(ckN[t], packNeg(d2, iRow));
                }
            }
#pragma unroll
            for (int off = 1; off <= 2; off <<= 1) {
                pKey = u64max(pKey, __shfl_xor_sync(0xFFFFFFFFu, pKey, off));
                nKey = u64min(nKey, __shfl_xor_sync(0xFFFFFFFFu, nKey, off));
            }
            if (q == 0) {
                sRowP[rl * 2 + warpN] = pKey;
                sRowN[rl * 2 + warpN] = nKey;
            }
        }
    }

    if (!diag) {
#pragma unroll
        for (int t = 0; t < 16; t++) {
#pragma unroll
            for (int off = 4; off <= 16; off <<= 1) {
                ckP[t] = u64max(ckP[t], __shfl_xor_sync(0xFFFFFFFFu, ckP[t], off));
                ckN[t] = u64min(ckN[t], __shfl_xor_sync(0xFFFFFFFFu, ckN[t], off));
            }
        }
        if (g == 0) {
#pragma unroll
            for (int t = 0; t < 16; t++) {
                int n8 = t >> 1, cc = t & 1;
                int jj = warpN * 64 + n8 * 8 + q * 2 + cc;
                sColP[jj * 2 + warpM] = ckP[t];
                sColN[jj * 2 + warpM] = ckN[t];
            }
        }
    }
    __syncthreads();

    if (tid < 128) {
        unsigned long long pKey = u64max(sRowP[tid * 2], sRowP[tid * 2 + 1]);
        unsigned long long nKey = u64min(sRowN[tid * 2], sRowN[tid * 2 + 1]);
        int iRow = iBase + tid;
        g_pos[bj][iRow] = pKey;
        g_neg[bj][iRow] = nKey;

        if (!diag) {
            unsigned long long cp = u64max(sColP[tid * 2], sColP[tid * 2 + 1]);
            unsigned long long cn = u64min(sColN[tid * 2], sColN[tid * 2 + 1]);
            int jRow = jBase + tid;
            g_pos[bi][jRow] = cp;
            g_neg[bi][jRow] = cn;
        }
    }
}

// ===================== kernel 3: fused merge + exact dp/dn loss =====================
__global__ __launch_bounds__(256) void lossKernel(const float* __restrict__ emb,
                                                  int D, int B) {
    int i = blockIdx.x;
    __shared__ int s_hp, s_hn, s_val;

    if (threadIdx.x < 32) {
        int c = threadIdx.x;    // NCHUNK == 32
        unsigned long long pKey = g_pos[c][i];
        unsigned long long nKey = g_neg[c][i];
#pragma unroll
        for (int off = 16; off > 0; off >>= 1) {
            pKey = u64max(pKey, __shfl_xor_sync(0xFFFFFFFFu, pKey, off));
            nKey = u64min(nKey, __shfl_xor_sync(0xFFFFFFFFu, nKey, off));
        }
        if (threadIdx.x == 0) {
            int hp = (int)(0xFFFFFFFFu - (uint32_t)pKey);
            int hn = (int)(uint32_t)nKey;
            int vp = (pKey != POS_EMPTY);
            int vn = (nKey != NEG_EMPTY);
            s_hp  = (vp && hp >= 0 && hp < B) ? hp : 0;
            s_hn  = (vn && hn >= 0 && hn < B) ? hn : 0;
            s_val = vp && vn;
        }
    }
    __syncthreads();

    int hp = s_hp, hn = s_hn;
    const float* a = emb + (size_t)i  * D;
    const float* p = emb + (size_t)hp * D;
    const float* n = emb + (size_t)hn * D;
    float sp = 0.f, sn = 0.f;
    for (int k = threadIdx.x * 4; k < D; k += blockDim.x * 4) {
        float4 va = *reinterpret_cast<const float4*>(a + k);
        float4 vp = *reinterpret_cast<const float4*>(p + k);
        float4 vn = *reinterpret_cast<const float4*>(n + k);
        float d;
        d = va.x - vp.x + 1e-6f; sp += d * d;
        d = va.y - vp.y + 1e-6f; sp += d * d;
        d = va.z - vp.z + 1e-6f; sp += d * d;
        d = va.w - vp.w + 1e-6f; sp += d * d;
        d = va.x - vn.x + 1e-6f; sn += d * d;
        d = va.y - vn.y + 1e-6f; sn += d * d;
        d = va.z - vn.z + 1e-6f; sn += d * d;
        d = va.w - vn.w + 1e-6f; sn += d * d;
    }
    for (int off = 16; off > 0; off >>= 1) {
        sp += __shfl_down_sync(0xFFFFFFFFu, sp, off);
        sn += __shfl_down_sync(0xFFFFFFFFu, sn, off);
    }
    __shared__ float wsp[8], wsn[8];
    int w = threadIdx.x >> 5;
    if ((threadIdx.x & 31) == 0) { wsp[w] = sp; wsn[w] = sn; }
    __syncthreads();
    if (threadIdx.x == 0) {
        float tp = 0.f, tn = 0.f;
#pragma unroll
        for (int ww = 0; ww < 8; ww++) { tp += wsp[ww]; tn += wsn[ww]; }
        float per = fmaxf(sqrtf(tp) - sqrtf(tn) + 0.3f, 0.f);
        g_loss[i]  = s_val ? per : 0.f;
        g_valid[i] = s_val;
    }
}

// ===================== kernel 4: final reduction (256 thr, vectorized) ==========
__global__ __launch_bounds__(256) void finalKernel(float* __restrict__ out, int B) {
    const int tid = threadIdx.x;
    float s = 0.f; int c = 0;
    // B/4 float4 / int4 elements, 256 threads
    const float4* lv = reinterpret_cast<const float4*>(g_loss);
    const int4*   cv = reinterpret_cast<const int4*>(g_valid);
    for (int k = tid; k < B / 4; k += 256) {
        float4 l = lv[k];
        int4   v = cv[k];
        s += l.x + l.y + l.z + l.w;
        c += v.x + v.y + v.z + v.w;
    }
    for (int off = 16; off > 0; off >>= 1) {
        s += __shfl_down_sync(0xFFFFFFFFu, s, off);
        c += __shfl_down_sync(0xFFFFFFFFu, c, off);
    }
    __shared__ float fs[8];
    __shared__ int   fc[8];
    if ((tid & 31) == 0) { fs[tid >> 5] = s; fc[tid >> 5] = c; }
    __syncthreads();
    if (tid == 0) {
        float ts = 0.f; int tc = 0;
#pragma unroll
        for (int ww = 0; ww < 8; ww++) { ts += fs[ww]; tc += fc[ww]; }
        out[0] = (tc > 0) ? ts / (float)tc : 0.f;
    }
}

// ===================== launch =====================
extern "C" void kernel_launch(void* const* d_in, const int* in_sizes, int n_in,
                              void* d_out, int out_size) {
    const float* emb    = (const float*)d_in[0];
    const int*   labels = (const int*)d_in[1];
    float*       out    = (float*)d_out;
    int B = in_sizes[1];
    int D = in_sizes[0] / B;

    cudaFuncSetAttribute(distKernel, cudaFuncAttributeMaxDynamicSharedMemorySize, SMEM_TOTAL);

    convKernel<<<B / 8, 256>>>(emb, D);
    int nb = B / BM;
    int ntiles = nb * (nb + 1) / 2;
    distKernel<<<ntiles, 128, SMEM_TOTAL>>>(labels, B, D);
    lossKernel<<<B, 256>>>(emb, D, B);
    finalKernel<<<1, 256>>>(out, B);
}